// round 9
// baseline (speedup 1.0000x reference)
#include <cuda_runtime.h>
#include <cuda_bf16.h>
#include <cfloat>
#include <cstdint>

#define BB 8
#define CC 64
#define NN 4096
#define OO 64
#define KNB 20
#define FULLMASK 0xffffffffu
#define MARG 2.0f

// Scratch (device globals: allocation-free per harness rules)
__device__ __nv_bfloat16 g_pdh[134217728]; // [B*N, N] approx pd (bf16), 268MB
__device__ float g_cmax[4194304];          // [B*N, 128] per-32-col-chunk max of approx
__device__ float g_sq[32768];              // [B*N] squared norms (exact fp32)
__device__ float g_xt[2097152];            // [B, N, C] transposed x, 8MB
__device__ float g_P[2097152];             // [B*N, O]  x·(W1-W2)^T
__device__ float g_Q[2097152];             // [B*N, O]  x·W2^T

#define LDM_X4(r0, r1, r2, r3, addr)                                         \
    asm volatile("ldmatrix.sync.aligned.m8n8.x4.shared.b16 {%0,%1,%2,%3}, [%4];" \
                 : "=r"(r0), "=r"(r1), "=r"(r2), "=r"(r3) : "r"(addr))

#define MMA16816(c, a, b0, b1)                                               \
    asm volatile("mma.sync.aligned.m16n8k16.row.col.f32.bf16.bf16.f32 "      \
                 "{%0,%1,%2,%3}, {%4,%5,%6,%7}, {%8,%9}, {%0,%1,%2,%3};"     \
                 : "+f"((c)[0]), "+f"((c)[1]), "+f"((c)[2]), "+f"((c)[3])    \
                 : "r"((a)[0]), "r"((a)[1]), "r"((a)[2]), "r"((a)[3]),       \
                   "r"(b0), "r"(b1))

// SMEM: A-tile 16KB @0, B-tile 16KB @16384; stage (bf16 [128][136]) overlays
// 0..34816 after MMA; sq vectors live above the stage.
#define SM_A0   0
#define SM_B0   16384
#define SM_SQN  34816
#define SM_SQM  35328
#define SM_TOT  35840
#define SP      136   // stage pitch in bf16 elems (mult of 4 -> 8B aligned rows)

__device__ __forceinline__ uint32_t smem_u32(const void* p) {
    uint32_t a;
    asm("{ .reg .u64 t; cvta.to.shared.u64 t, %1; cvt.u32.u64 %0, t; }"
        : "=r"(a) : "l"(p));
    return a;
}

// ---------------------------------------------------------------------------
// Kernel 1: squared norms (exact fp32, ascending-c fmaf chain)
// ---------------------------------------------------------------------------
__global__ void sq_kernel(const float* __restrict__ x) {
    int t = blockIdx.x * blockDim.x + threadIdx.x;
    int b = t >> 12, n = t & 4095;
    const float* xp = x + (size_t)b * CC * NN + n;
    float s = 0.f;
    #pragma unroll
    for (int c = 0; c < CC; ++c) {
        float v = xp[(size_t)c * NN];
        s = fmaf(v, v, s);
    }
    g_sq[t] = s;
}

// ---------------------------------------------------------------------------
// Kernel 1b: xt[b][n][c] = x[b][c][n] (exact copy for candidate rescoring)
// ---------------------------------------------------------------------------
__global__ void xt_kernel(const float* __restrict__ x) {
    __shared__ float tile[32][33];
    int b = blockIdx.z;
    int c0 = blockIdx.y * 32, n0 = blockIdx.x * 32;
    int tx = threadIdx.x, ty = threadIdx.y;   // 32 x 8
    #pragma unroll
    for (int i = 0; i < 32; i += 8)
        tile[ty + i][tx] = x[(size_t)b * CC * NN + (size_t)(c0 + ty + i) * NN + n0 + tx];
    __syncthreads();
    #pragma unroll
    for (int i = 0; i < 32; i += 8)
        g_xt[(size_t)b * NN * CC + (size_t)(n0 + ty + i) * CC + c0 + tx] = tile[tx][ty + i];
}

// ---------------------------------------------------------------------------
// Kernel 2: P = x·(W1-W2)^T, Q = x·W2^T
// ---------------------------------------------------------------------------
__global__ __launch_bounds__(256) void pq_kernel(const float* __restrict__ x,
                                                 const float* __restrict__ W) {
    __shared__ float Wa[CC][OO + 1];
    __shared__ float Wb[CC][OO + 1];
    __shared__ float xs[CC][4];
    int tid = threadIdx.x;
    #pragma unroll
    for (int i = 0; i < 16; ++i) {
        int fid = tid + i * 256;
        int o = fid >> 6, c = fid & 63;
        float w1 = W[o * 128 + c];
        float w2 = W[o * 128 + 64 + c];
        Wa[c][o] = w1 - w2;
        Wb[c][o] = w2;
    }
    int nbase = blockIdx.x * 4;
    int b = nbase >> 12;
    int nb = nbase & 4095;
    {
        int c = tid >> 2, j = tid & 3;
        xs[c][j] = x[(size_t)b * CC * NN + (size_t)c * NN + nb + j];
    }
    __syncthreads();
    int o = tid & 63, nl = tid >> 6;
    float p = 0.f, q = 0.f;
    #pragma unroll
    for (int c = 0; c < CC; ++c) {
        float xv = xs[c][nl];
        p = fmaf(xv, Wa[c][o], p);
        q = fmaf(xv, Wb[c][o], q);
    }
    size_t g = (size_t)(nbase + nl);
    g_P[g * OO + o] = p;
    g_Q[g * OO + o] = q;
}

// ---------------------------------------------------------------------------
// Kernel 3: pd SCREEN via single-term bf16 HMMA (approx, err <= ~1.6 absolute).
// Triangular grid per batch (blockIdx.z = b), mirror store, bf16 values +
// fp32 per-32-col chunkmax of the STORED approx values.
// ---------------------------------------------------------------------------
__global__ __launch_bounds__(256) void pd_screen(const float* __restrict__ x) {
    extern __shared__ char sm[];
    uint32_t sb = smem_u32(sm);
    int tid = threadIdx.x, lane = tid & 31, wid = tid >> 5;
    int b = blockIdx.z;

    int t = blockIdx.x;
    int mt = (int)((sqrtf(8.f * (float)t + 1.f) - 1.f) * 0.5f);
    while ((mt + 1) * (mt + 2) / 2 <= t) ++mt;
    while (mt * (mt + 1) / 2 > t) --mt;
    int nt = t - mt * (mt + 1) / 2;
    int n0 = nt * 128, m0 = mt * 128;

    // load + round-to-bf16 both tiles (h term only), swizzled K-major
    const float* xb = x + (size_t)b * CC * NN;
    {
        int side = tid >> 7;
        int row  = tid & 127;
        int p0 = side ? m0 : n0;
        char* hb = sm + (side ? SM_B0 : SM_A0);
        #pragma unroll 8
        for (int c = 0; c < CC; c += 2) {
            float v0 = xb[(size_t)c * NN + p0 + row];
            float v1 = xb[(size_t)(c + 1) * NN + p0 + row];
            __nv_bfloat162 hh;
            hh.x = __float2bfloat16(v0);
            hh.y = __float2bfloat16(v1);
            uint32_t off = (uint32_t)(row * 128 + c * 2);
            off = off ^ ((off >> 3) & 0x70);
            *(__nv_bfloat162*)(hb + off) = hh;
        }
    }
    if (tid < 128)       ((float*)(sm + SM_SQN))[tid]       = g_sq[b * NN + n0 + tid];
    else                 ((float*)(sm + SM_SQM))[tid - 128] = g_sq[b * NN + m0 + (tid - 128)];
    __syncthreads();

    // warp tiling 2x4, warp tile 64x32
    int wr = wid >> 2, wc = wid & 3;
    float acc[4][4][4];
    #pragma unroll
    for (int mi = 0; mi < 4; ++mi)
        #pragma unroll
        for (int ni = 0; ni < 4; ++ni)
            #pragma unroll
            for (int q = 0; q < 4; ++q) acc[mi][ni][q] = 0.f;

    int gA = lane >> 3;
    int rowA_add = (gA & 1) * 8 + (lane & 7);
    int kA_add   = (gA >> 1) * 16;
    uint32_t xorA = (uint32_t)(rowA_add & 7) << 4;
    int gB = lane >> 3;
    int rowB_add = (gB >> 1) * 8 + (lane & 7);
    int kB_add   = (gB & 1) * 16;
    uint32_t xorB = (uint32_t)(rowB_add & 7) << 4;

    #pragma unroll
    for (int ks = 0; ks < 4; ++ks) {
        int kb = ks * 32;
        uint32_t afr[4][4];
        #pragma unroll
        for (int mi = 0; mi < 4; ++mi) {
            int row = wr * 64 + mi * 16 + rowA_add;
            uint32_t addr = (sb + SM_A0 + (uint32_t)(row * 128 + kb + kA_add)) ^ xorA;
            LDM_X4(afr[mi][0], afr[mi][1], afr[mi][2], afr[mi][3], addr);
        }
        uint32_t bfr[4][2];
        #pragma unroll
        for (int np = 0; np < 2; ++np) {
            int row = wc * 32 + np * 16 + rowB_add;
            uint32_t addr = (sb + SM_B0 + (uint32_t)(row * 128 + kb + kB_add)) ^ xorB;
            LDM_X4(bfr[np * 2][0], bfr[np * 2][1],
                   bfr[np * 2 + 1][0], bfr[np * 2 + 1][1], addr);
        }
        #pragma unroll
        for (int mi = 0; mi < 4; ++mi)
            #pragma unroll
            for (int ni = 0; ni < 4; ++ni)
                MMA16816(acc[mi][ni], afr[mi], bfr[ni][0], bfr[ni][1]);
    }
    __syncthreads();

    // stage 2*acc - sqn - sqm as bf16 into [128][SP]
    const float* sqn = (const float*)(sm + SM_SQN);
    const float* sqm = (const float*)(sm + SM_SQM);
    __nv_bfloat16* stage = (__nv_bfloat16*)sm;
    {
        int g = lane >> 2, tg = lane & 3;
        #pragma unroll
        for (int mi = 0; mi < 4; ++mi) {
            int r0 = wr * 64 + mi * 16 + g;
            float sn0 = sqn[r0], sn1 = sqn[r0 + 8];
            #pragma unroll
            for (int ni = 0; ni < 4; ++ni) {
                int col = wc * 32 + ni * 8 + tg * 2;
                float sm0 = sqm[col], sm1 = sqm[col + 1];
                __nv_bfloat162 u, v;
                u.x = __float2bfloat16(2.f * acc[mi][ni][0] - sn0 - sm0);
                u.y = __float2bfloat16(2.f * acc[mi][ni][1] - sn0 - sm1);
                v.x = __float2bfloat16(2.f * acc[mi][ni][2] - sn1 - sm0);
                v.y = __float2bfloat16(2.f * acc[mi][ni][3] - sn1 - sm1);
                *(__nv_bfloat162*)&stage[r0 * SP + col]       = u;
                *(__nv_bfloat162*)&stage[(r0 + 8) * SP + col] = v;
            }
        }
    }
    __syncthreads();

    // copy-out normal rows + chunkmax (max of stored bf16 values)
    int row = tid >> 1, half = tid & 1;
    __nv_bfloat16* outp = g_pdh + ((size_t)(b * NN + n0 + row)) * NN + m0 + half * 64;
    float* cmn = g_cmax + (size_t)(b * NN + n0 + row) * 128 + mt * 4 + half * 2;
    {
        float c0 = -FLT_MAX, c1 = -FLT_MAX;
        #pragma unroll
        for (int q = 0; q < 16; ++q) {
            uint2 raw = *(uint2*)&stage[row * SP + half * 64 + q * 4];
            __nv_bfloat162 p0 = *(__nv_bfloat162*)&raw.x;
            __nv_bfloat162 p1 = *(__nv_bfloat162*)&raw.y;
            float mx = fmaxf(fmaxf(__bfloat162float(p0.x), __bfloat162float(p0.y)),
                             fmaxf(__bfloat162float(p1.x), __bfloat162float(p1.y)));
            if (q < 8) c0 = fmaxf(c0, mx); else c1 = fmaxf(c1, mx);
            *(uint2*)&outp[q * 4] = raw;
        }
        cmn[0] = c0;
        cmn[1] = c1;
    }

    // mirror (skip diagonal)
    if (nt != mt) {
        int mr = row;
        __nv_bfloat16* outq = g_pdh + ((size_t)(b * NN + m0 + mr)) * NN + n0 + half * 64;
        float* cmm = g_cmax + (size_t)(b * NN + m0 + mr) * 128 + nt * 4 + half * 2;
        float c0 = -FLT_MAX, c1 = -FLT_MAX;
        #pragma unroll 4
        for (int q = 0; q < 16; ++q) {
            int jb = half * 64 + q * 4;
            __nv_bfloat16 e0 = stage[(jb + 0) * SP + mr];
            __nv_bfloat16 e1 = stage[(jb + 1) * SP + mr];
            __nv_bfloat16 e2 = stage[(jb + 2) * SP + mr];
            __nv_bfloat16 e3 = stage[(jb + 3) * SP + mr];
            float mx = fmaxf(fmaxf(__bfloat162float(e0), __bfloat162float(e1)),
                             fmaxf(__bfloat162float(e2), __bfloat162float(e3)));
            if (q < 8) c0 = fmaxf(c0, mx); else c1 = fmaxf(c1, mx);
            __nv_bfloat162 lo; lo.x = e0; lo.y = e1;
            __nv_bfloat162 hi; hi.x = e2; hi.y = e3;
            uint2 raw;
            raw.x = *(uint32_t*)&lo;
            raw.y = *(uint32_t*)&hi;
            *(uint2*)&outq[q * 4] = raw;
        }
        cmm[0] = c0;
        cmm[1] = c1;
    }
}

// ---------------------------------------------------------------------------
// Kernel 4: warp-per-row top-20: chunkmax-gated scan of approx bf16 values
// with margin MARG; each surviving candidate is rescored EXACTLY in fp32
// (ascending-c fmaf == sq order, so self-pd == 0 exactly) before insertion.
// Fused gather + BN affine + leaky-relu + max-over-k + transposed store.
// ---------------------------------------------------------------------------
__global__ __launch_bounds__(256) void topk_fused(
    const float* __restrict__ gamma, const float* __restrict__ beta,
    const float* __restrict__ rmean, const float* __restrict__ rvar,
    float* __restrict__ out)
{
    __shared__ float rowv[8][64];
    int warp = threadIdx.x >> 5, lane = threadIdx.x & 31;
    int row = blockIdx.x * 8 + warp;
    int b = row >> 12, n = row & 4095;

    const float* cmrow = g_cmax + (size_t)row * 128;
    float cm[4];
    #pragma unroll
    for (int j = 0; j < 4; ++j) cm[j] = __ldg(&cmrow[j * 32 + lane]);
    float lmax = fmaxf(fmaxf(cm[0], cm[1]), fmaxf(cm[2], cm[3]));

    // bitonic sort 32 lane-group maxes
    float s = lmax;
    #pragma unroll
    for (int k2 = 2; k2 <= 32; k2 <<= 1) {
        #pragma unroll
        for (int j2 = k2 >> 1; j2 > 0; j2 >>= 1) {
            float o = __shfl_xor_sync(FULLMASK, s, j2);
            bool dirAsc = ((lane & k2) == 0);
            bool upper  = ((lane & j2) == 0);
            float mn = fminf(s, o), mx = fmaxf(s, o);
            s = (dirAsc == upper) ? mn : mx;
        }
    }
    float T0 = __shfl_sync(FULLMASK, s, 32 - KNB);
    float Tgate = T0 - 2.f * MARG;    // any true top-20 has approx >= Tgate

    // row vector for exact rescoring
    rowv[warp][lane]      = g_xt[(size_t)row * CC + lane];
    rowv[warp][lane + 32] = g_xt[(size_t)row * CC + 32 + lane];
    __syncwarp();
    const float* xtb = g_xt + (size_t)b * NN * CC;
    float sqr = g_sq[row];
    const float* sqb = g_sq + b * NN;

    float lv = -FLT_MAX;
    int   li = 0;
    float vmin = -FLT_MAX;
    int   minpos = 0;
    const __nv_bfloat16* rowh = g_pdh + (size_t)row * NN;

    #pragma unroll
    for (int j = 0; j < 4; ++j) {
        unsigned cmask = __ballot_sync(FULLMASK, cm[j] >= Tgate);
        while (cmask) {
            int q = __ffs(cmask) - 1;
            cmask &= cmask - 1;
            float cmv = __shfl_sync(FULLMASK, cm[j], q);
            if (vmin > -FLT_MAX && cmv <= vmin - MARG) continue;   // can't beat
            int chunk = j * 32 + q;
            float va = __bfloat162float(rowh[chunk * 32 + lane]);
            bool cand = (va >= Tgate) && (va > vmin - MARG);
            float ve = -FLT_MAX;
            int   ci = chunk * 32 + lane;
            if (cand) {
                const float4* cp = (const float4*)(xtb + (size_t)ci * CC);
                float acc = 0.f;
                #pragma unroll
                for (int qq = 0; qq < 16; ++qq) {
                    float4 c4 = __ldg(&cp[qq]);
                    acc = fmaf(c4.x, rowv[warp][qq * 4 + 0], acc);
                    acc = fmaf(c4.y, rowv[warp][qq * 4 + 1], acc);
                    acc = fmaf(c4.z, rowv[warp][qq * 4 + 2], acc);
                    acc = fmaf(c4.w, rowv[warp][qq * 4 + 3], acc);
                }
                ve = 2.f * acc - sqr - __ldg(&sqb[ci]);
            }
            unsigned m = __ballot_sync(FULLMASK, ve > vmin);
            while (m) {
                int lead = __ffs(m) - 1;
                float cv = __shfl_sync(FULLMASK, ve, lead);
                int   cix = __shfl_sync(FULLMASK, ci, lead);
                if (lane == minpos) { lv = cv; li = cix; }
                float tt = (lane < KNB) ? lv : FLT_MAX;
                #pragma unroll
                for (int off = 16; off; off >>= 1)
                    tt = fminf(tt, __shfl_xor_sync(FULLMASK, tt, off));
                vmin = tt;
                minpos = __ffs(__ballot_sync(FULLMASK, lane < KNB && lv == vmin)) - 1;
                m &= ~(1u << lead);
                m &= __ballot_sync(FULLMASK, ve > vmin);
            }
        }
    }

    // fused epilogue: out[b,o,n] = max_k leaky(BN(P[row,o] + Q[idx_k,o]))
    float sc1 = gamma[lane]      * rsqrtf(rvar[lane]      + 1e-5f);
    float sc2 = gamma[lane + 32] * rsqrtf(rvar[lane + 32] + 1e-5f);
    float bi1 = beta[lane]      - rmean[lane]      * sc1;
    float bi2 = beta[lane + 32] - rmean[lane + 32] * sc2;
    float p1 = g_P[(size_t)row * OO + lane];
    float p2 = g_P[(size_t)row * OO + lane + 32];
    const float* Qb = g_Q + (size_t)b * NN * OO;

    float m1 = -FLT_MAX, m2 = -FLT_MAX;
    #pragma unroll
    for (int kk = 0; kk < KNB; ++kk) {
        int nid = __shfl_sync(FULLMASK, li, kk);
        const float* Qr = Qb + (size_t)nid * OO;
        float y1 = (p1 + __ldg(&Qr[lane]))      * sc1 + bi1;
        float y2 = (p2 + __ldg(&Qr[lane + 32])) * sc2 + bi2;
        y1 = (y1 >= 0.f) ? y1 : 0.2f * y1;
        y2 = (y2 >= 0.f) ? y2 : 0.2f * y2;
        m1 = fmaxf(m1, y1);
        m2 = fmaxf(m2, y2);
    }
    out[((size_t)b * OO + lane)      * NN + n] = m1;
    out[((size_t)b * OO + lane + 32) * NN + n] = m2;
}

// ---------------------------------------------------------------------------
extern "C" void kernel_launch(void* const* d_in, const int* in_sizes, int n_in,
                              void* d_out, int out_size) {
    const float* x     = (const float*)d_in[0];
    const float* W     = (const float*)d_in[1];
    const float* gamma = (const float*)d_in[2];
    const float* beta  = (const float*)d_in[3];
    const float* rmean = (const float*)d_in[4];
    const float* rvar  = (const float*)d_in[5];
    float* out = (float*)d_out;

    sq_kernel<<<128, 256>>>(x);
    xt_kernel<<<dim3(NN / 32, CC / 32, BB), dim3(32, 8)>>>(x);
    pq_kernel<<<8192, 256>>>(x, W);
    pd_screen<<<dim3(528, 1, BB), 256, SM_TOT>>>(x);
    topk_fused<<<4096, 256>>>(gamma, beta, rmean, rvar, out);
}

// round 10
// speedup vs baseline: 1.6222x; 1.6222x over previous
#include <cuda_runtime.h>
#include <cfloat>
#include <cstdint>

#define BB 8
#define CC 64
#define NN 4096
#define OO 64
#define KNB 20
#define FULLMASK 0xffffffffu

// Scratch (device globals: allocation-free per harness rules)
__device__ float g_pd[134217728];   // [B*N, N] pairwise "distance", 537MB
__device__ float g_cmax[4194304];   // [B*N, 128] per-32-col-chunk max, 16MB
__device__ float g_sq[32768];       // [B*N] squared norms
__device__ float g_P[2097152];      // [B*N, O]  x·(W1-W2)^T
__device__ float g_Q[2097152];      // [B*N, O]  x·W2^T

// packed f32x2 FMA: d = a*b + d, elementwise on two fp32 lanes (IEEE .rn each)
__device__ __forceinline__ void ffma2(unsigned long long& d,
                                      unsigned long long a,
                                      unsigned long long b) {
    asm("fma.rn.f32x2 %0, %1, %2, %0;" : "+l"(d) : "l"(a), "l"(b));
}
__device__ __forceinline__ unsigned long long dup2(float v) {
    unsigned long long r;
    asm("mov.b64 %0, {%1, %1};" : "=l"(r) : "r"(__float_as_uint(v)));
    return r;
}

// ---------------------------------------------------------------------------
// Kernel 1: squared norms. sq[b,n] = sum_c x[b,c,n]^2 (same FMA order as GEMM)
// ---------------------------------------------------------------------------
__global__ void sq_kernel(const float* __restrict__ x) {
    int t = blockIdx.x * blockDim.x + threadIdx.x;   // 0..32767
    int b = t >> 12, n = t & 4095;
    const float* xp = x + (size_t)b * CC * NN + n;
    float s = 0.f;
    #pragma unroll
    for (int c = 0; c < CC; ++c) {
        float v = xp[(size_t)c * NN];
        s = fmaf(v, v, s);
    }
    g_sq[t] = s;
}

// ---------------------------------------------------------------------------
// Kernel 2: P = x·(W1-W2)^T, Q = x·W2^T   (collapses the edge GEMM)
// ---------------------------------------------------------------------------
__global__ __launch_bounds__(256) void pq_kernel(const float* __restrict__ x,
                                                 const float* __restrict__ W) {
    __shared__ float Wa[CC][OO + 1];
    __shared__ float Wb[CC][OO + 1];
    __shared__ float xs[CC][4];
    int tid = threadIdx.x;
    #pragma unroll
    for (int i = 0; i < 16; ++i) {
        int fid = tid + i * 256;
        int o = fid >> 6, c = fid & 63;
        float w1 = W[o * 128 + c];
        float w2 = W[o * 128 + 64 + c];
        Wa[c][o] = w1 - w2;
        Wb[c][o] = w2;
    }
    int nbase = blockIdx.x * 4;
    int b = nbase >> 12;
    int nb = nbase & 4095;
    {
        int c = tid >> 2, j = tid & 3;
        xs[c][j] = x[(size_t)b * CC * NN + (size_t)c * NN + nb + j];
    }
    __syncthreads();
    int o = tid & 63, nl = tid >> 6;
    float p = 0.f, q = 0.f;
    #pragma unroll
    for (int c = 0; c < CC; ++c) {
        float xv = xs[c][nl];
        p = fmaf(xv, Wa[c][o], p);
        q = fmaf(xv, Wb[c][o], q);
    }
    size_t g = (size_t)(nbase + nl);
    g_P[g * OO + o] = p;
    g_Q[g * OO + o] = q;
}

// ---------------------------------------------------------------------------
// Kernel 3: symmetric pd GEMM with packed f32x2 FMA mainloop.
// Triangular grid (528 tiles, one batch per launch), mirror-stores, emits
// per-32-col chunkmax. Same FMA c-order as sq_kernel => diagonal exactly 0.
// ---------------------------------------------------------------------------
__global__ __launch_bounds__(256) void pd_gemm_sym(const float* __restrict__ x,
                                                   int b) {
    // linear tile id -> (nt <= mt), t = mt(mt+1)/2 + nt
    int t = blockIdx.x;
    int mt = (int)((sqrtf(8.f * (float)t + 1.f) - 1.f) * 0.5f);
    while ((mt + 1) * (mt + 2) / 2 <= t) ++mt;
    while (mt * (mt + 1) / 2 > t) --mt;
    int nt = t - mt * (mt + 1) / 2;

    __shared__ float As[CC][128];
    __shared__ float Bs[CC][128];
    __shared__ float sqn[128], sqm[128];
    __shared__ float stg[16][128];     // mirror-side chunkmax staging

    int n0 = nt * 128, m0 = mt * 128;
    const float* xb = x + (size_t)b * CC * NN;
    int tid = threadIdx.x;

    #pragma unroll
    for (int i = 0; i < 8; ++i) {
        int fid = tid + i * 256;
        int c = fid >> 5, v = (fid & 31) << 2;
        *(float4*)&As[c][v] = *(const float4*)&xb[(size_t)c * NN + n0 + v];
        *(float4*)&Bs[c][v] = *(const float4*)&xb[(size_t)c * NN + m0 + v];
    }
    if (tid < 128)       sqn[tid]       = g_sq[b * NN + n0 + tid];
    else                 sqm[tid - 128] = g_sq[b * NN + m0 + (tid - 128)];
    __syncthreads();

    int tx = tid & 15, ty = tid >> 4;

    // packed accumulators: acc2[i][jp] holds cols (2jp, 2jp+1) for row i
    unsigned long long acc2[8][4];
    #pragma unroll
    for (int i = 0; i < 8; ++i)
        #pragma unroll
        for (int jp = 0; jp < 4; ++jp) acc2[i][jp] = 0ull;

    #pragma unroll 4
    for (int c = 0; c < CC; ++c) {
        float ar[8];
        *(float4*)&ar[0] = *(float4*)&As[c][ty * 8];
        *(float4*)&ar[4] = *(float4*)&As[c][ty * 8 + 4];
        ulonglong2 bl = *(ulonglong2*)&Bs[c][tx * 8];
        ulonglong2 bh = *(ulonglong2*)&Bs[c][tx * 8 + 4];
        unsigned long long br2[4] = {bl.x, bl.y, bh.x, bh.y};
        #pragma unroll
        for (int i = 0; i < 8; ++i) {
            unsigned long long ad = dup2(ar[i]);
            #pragma unroll
            for (int jp = 0; jp < 4; ++jp)
                ffma2(acc2[i][jp], ad, br2[jp]);
        }
    }

    // unpack accumulators into acc[i][j]
    float acc[8][8];
    #pragma unroll
    for (int i = 0; i < 8; ++i)
        #pragma unroll
        for (int jp = 0; jp < 4; ++jp) {
            float2 f = *(float2*)&acc2[i][jp];
            acc[i][jp * 2]     = f.x;
            acc[i][jp * 2 + 1] = f.y;
        }

    // normal store: tile [n0.., m0..] + n-side chunk maxima
    float* outp = g_pd + ((size_t)(b * NN + n0)) * NN + m0;
    float* cmn  = g_cmax + ((size_t)(b * NN + n0)) * 128 + (m0 >> 5);
    #pragma unroll
    for (int i = 0; i < 8; ++i) {
        int r = ty * 8 + i;
        float sn = sqn[r];
        float res[8];
        #pragma unroll
        for (int j = 0; j < 8; ++j)
            res[j] = 2.f * acc[i][j] - sn - sqm[tx * 8 + j];
        *(float4*)&outp[(size_t)r * NN + tx * 8]     = *(float4*)&res[0];
        *(float4*)&outp[(size_t)r * NN + tx * 8 + 4] = *(float4*)&res[4];
        float rm = fmaxf(fmaxf(fmaxf(res[0], res[1]), fmaxf(res[2], res[3])),
                         fmaxf(fmaxf(res[4], res[5]), fmaxf(res[6], res[7])));
        rm = fmaxf(rm, __shfl_xor_sync(FULLMASK, rm, 1));
        rm = fmaxf(rm, __shfl_xor_sync(FULLMASK, rm, 2));
        if ((tx & 3) == 0)
            cmn[(size_t)r * 128 + (tx >> 2)] = rm;
    }

    // mirror store: tile [m0.., n0..] + m-side chunk maxima (skip on diagonal)
    if (nt != mt) {
        float* outq = g_pd + ((size_t)(b * NN + m0)) * NN + n0;
        #pragma unroll
        for (int j = 0; j < 8; ++j) {
            int rm = tx * 8 + j;
            float sm = sqm[rm];
            float4 lo, hi;
            lo.x = 2.f * acc[0][j] - sqn[ty * 8 + 0] - sm;
            lo.y = 2.f * acc[1][j] - sqn[ty * 8 + 1] - sm;
            lo.z = 2.f * acc[2][j] - sqn[ty * 8 + 2] - sm;
            lo.w = 2.f * acc[3][j] - sqn[ty * 8 + 3] - sm;
            hi.x = 2.f * acc[4][j] - sqn[ty * 8 + 4] - sm;
            hi.y = 2.f * acc[5][j] - sqn[ty * 8 + 5] - sm;
            hi.z = 2.f * acc[6][j] - sqn[ty * 8 + 6] - sm;
            hi.w = 2.f * acc[7][j] - sqn[ty * 8 + 7] - sm;
            *(float4*)&outq[(size_t)rm * NN + ty * 8]     = lo;
            *(float4*)&outq[(size_t)rm * NN + ty * 8 + 4] = hi;
            float cm = fmaxf(fmaxf(fmaxf(lo.x, lo.y), fmaxf(lo.z, lo.w)),
                             fmaxf(fmaxf(hi.x, hi.y), fmaxf(hi.z, hi.w)));
            stg[ty][rm] = cm;
        }
        __syncthreads();
        if (tid < 128) {
            int col = tid;   // mirror row m0+col
            float* cmm = g_cmax + ((size_t)(b * NN + m0 + col)) * 128 + (n0 >> 5);
            #pragma unroll
            for (int g = 0; g < 4; ++g) {
                float v = fmaxf(fmaxf(stg[g * 4 + 0][col], stg[g * 4 + 1][col]),
                                fmaxf(stg[g * 4 + 2][col], stg[g * 4 + 3][col]));
                cmm[g] = v;
            }
        }
    }
}

// ---------------------------------------------------------------------------
// Kernel 4: warp-per-row top-20 using precomputed chunk maxima, per batch.
// Fused with gather + BN affine + leaky-relu + max-over-k + transposed store.
// ---------------------------------------------------------------------------
__global__ __launch_bounds__(256) void topk_fused(
    const float* __restrict__ gamma, const float* __restrict__ beta,
    const float* __restrict__ rmean, const float* __restrict__ rvar,
    float* __restrict__ out, int b)
{
    int warp = threadIdx.x >> 5, lane = threadIdx.x & 31;
    int n = blockIdx.x * 8 + warp;          // 0..4095
    int row = b * NN + n;

    const float* cmrow = g_cmax + (size_t)row * 128;
    float cm[4];
    #pragma unroll
    for (int j = 0; j < 4; ++j) cm[j] = __ldg(&cmrow[j * 32 + lane]);
    float lmax = fmaxf(fmaxf(cm[0], cm[1]), fmaxf(cm[2], cm[3]));

    // bitonic sort 32 lane-group maxes ascending across lanes
    float s = lmax;
    #pragma unroll
    for (int k2 = 2; k2 <= 32; k2 <<= 1) {
        #pragma unroll
        for (int j2 = k2 >> 1; j2 > 0; j2 >>= 1) {
            float o = __shfl_xor_sync(FULLMASK, s, j2);
            bool dirAsc = ((lane & k2) == 0);
            bool upper  = ((lane & j2) == 0);
            float mn = fminf(s, o), mx = fmaxf(s, o);
            s = (dirAsc == upper) ? mn : mx;
        }
    }
    float T0 = __shfl_sync(FULLMASK, s, 32 - KNB);   // 20th largest lane-group max

    float lv = -FLT_MAX;
    int   li = 0;
    float vmin = -FLT_MAX;
    int   minpos = 0;
    const float* rowf = g_pd + (size_t)row * NN;

    #pragma unroll
    for (int j = 0; j < 4; ++j) {
        unsigned cmask = __ballot_sync(FULLMASK, cm[j] >= T0);
        while (cmask) {
            int q = __ffs(cmask) - 1;
            cmask &= cmask - 1;
            float cmv = __shfl_sync(FULLMASK, cm[j], q);
            if (cmv <= vmin && vmin > -FLT_MAX) continue;   // can't beat list
            int chunk = j * 32 + q;
            float v = __ldg(&rowf[chunk * 32 + lane]);
            unsigned m = __ballot_sync(FULLMASK, v >= T0 && v > vmin);
            while (m) {
                int lead = __ffs(m) - 1;
                float cv = __shfl_sync(FULLMASK, v, lead);
                int   ci = chunk * 32 + lead;
                if (lane == minpos) { lv = cv; li = ci; }
                float tt = (lane < KNB) ? lv : FLT_MAX;
                #pragma unroll
                for (int off = 16; off; off >>= 1)
                    tt = fminf(tt, __shfl_xor_sync(FULLMASK, tt, off));
                vmin = tt;
                minpos = __ffs(__ballot_sync(FULLMASK, lane < KNB && lv == vmin)) - 1;
                m &= ~(1u << lead);
                m &= __ballot_sync(FULLMASK, v > vmin);
            }
        }
    }

    float sc1 = gamma[lane]      * rsqrtf(rvar[lane]      + 1e-5f);
    float sc2 = gamma[lane + 32] * rsqrtf(rvar[lane + 32] + 1e-5f);
    float bi1 = beta[lane]      - rmean[lane]      * sc1;
    float bi2 = beta[lane + 32] - rmean[lane + 32] * sc2;
    float p1 = g_P[(size_t)row * OO + lane];
    float p2 = g_P[(size_t)row * OO + lane + 32];
    const float* Qb = g_Q + (size_t)b * NN * OO;

    float m1 = -FLT_MAX, m2 = -FLT_MAX;
    #pragma unroll
    for (int kk = 0; kk < KNB; ++kk) {
        int nid = __shfl_sync(FULLMASK, li, kk);
        const float* Qr = Qb + (size_t)nid * OO;
        float y1 = (p1 + __ldg(&Qr[lane]))      * sc1 + bi1;
        float y2 = (p2 + __ldg(&Qr[lane + 32])) * sc2 + bi2;
        y1 = (y1 >= 0.f) ? y1 : 0.2f * y1;
        y2 = (y2 >= 0.f) ? y2 : 0.2f * y2;
        m1 = fmaxf(m1, y1);
        m2 = fmaxf(m2, y2);
    }
    out[((size_t)b * OO + lane)      * NN + n] = m1;
    out[((size_t)b * OO + lane + 32) * NN + n] = m2;
}

// ---------------------------------------------------------------------------
// Launcher: pd(b) on the capture stream; topk(b) on a side stream forked via
// events, so topk(b) overlaps pd(b+1). Join back before returning.
// ---------------------------------------------------------------------------
extern "C" void kernel_launch(void* const* d_in, const int* in_sizes, int n_in,
                              void* d_out, int out_size) {
    const float* x     = (const float*)d_in[0];
    const float* W     = (const float*)d_in[1];
    const float* gamma = (const float*)d_in[2];
    const float* beta  = (const float*)d_in[3];
    const float* rmean = (const float*)d_in[4];
    const float* rvar  = (const float*)d_in[5];
    float* out = (float*)d_out;

    static cudaStream_t s1;
    static cudaEvent_t evPd[BB], evJoin;
    static int inited = 0;
    if (!inited) {
        cudaStreamCreateWithFlags(&s1, cudaStreamNonBlocking);
        for (int i = 0; i < BB; ++i)
            cudaEventCreateWithFlags(&evPd[i], cudaEventDisableTiming);
        cudaEventCreateWithFlags(&evJoin, cudaEventDisableTiming);
        inited = 1;
    }

    // stream 0 = the (capture) stream the harness calls us on: default stream
    sq_kernel<<<128, 256>>>(x);
    pq_kernel<<<8192, 256>>>(x, W);

    for (int b = 0; b < BB; ++b) {
        pd_gemm_sym<<<528, 256>>>(x, b);
        cudaEventRecord(evPd[b], 0);
        cudaStreamWaitEvent(s1, evPd[b], 0);
        topk_fused<<<512, 256, 0, s1>>>(gamma, beta, rmean, rvar, out, b);
    }
    cudaEventRecord(evJoin, s1);
    cudaStreamWaitEvent(0, evJoin, 0);
}

// round 11
// speedup vs baseline: 1.9854x; 1.2239x over previous
#include <cuda_runtime.h>
#include <cfloat>
#include <cstdint>

#define BB 8
#define CC 64
#define NN 4096
#define OO 64
#define KNB 20
#define FULLMASK 0xffffffffu

// Scratch (device globals: allocation-free per harness rules)
__device__ float g_pd[134217728];   // [B*N, N] pairwise "distance", 537MB
__device__ float g_cmax[4194304];   // [B*N, 128] per-32-col-chunk max, 16MB
__device__ float g_sq[32768];       // [B*N] squared norms
__device__ float g_P[2097152];      // [B*N, O]  x·(W1-W2)^T
__device__ float g_Q[2097152];      // [B*N, O]  x·W2^T

// ---------------------------------------------------------------------------
// Kernel 1: squared norms. sq[b,n] = sum_c x[b,c,n]^2 (same FMA order as GEMM)
// ---------------------------------------------------------------------------
__global__ void sq_kernel(const float* __restrict__ x) {
    int t = blockIdx.x * blockDim.x + threadIdx.x;   // 0..32767
    int b = t >> 12, n = t & 4095;
    const float* xp = x + (size_t)b * CC * NN + n;
    float s = 0.f;
    #pragma unroll
    for (int c = 0; c < CC; ++c) {
        float v = xp[(size_t)c * NN];
        s = fmaf(v, v, s);
    }
    g_sq[t] = s;
}

// ---------------------------------------------------------------------------
// Kernel 2: P = x·(W1-W2)^T, Q = x·W2^T   (collapses the edge GEMM)
// ---------------------------------------------------------------------------
__global__ __launch_bounds__(256) void pq_kernel(const float* __restrict__ x,
                                                 const float* __restrict__ W) {
    __shared__ float Wa[CC][OO + 1];
    __shared__ float Wb[CC][OO + 1];
    __shared__ float xs[CC][4];
    int tid = threadIdx.x;
    #pragma unroll
    for (int i = 0; i < 16; ++i) {
        int fid = tid + i * 256;
        int o = fid >> 6, c = fid & 63;
        float w1 = W[o * 128 + c];
        float w2 = W[o * 128 + 64 + c];
        Wa[c][o] = w1 - w2;
        Wb[c][o] = w2;
    }
    int nbase = blockIdx.x * 4;
    int b = nbase >> 12;
    int nb = nbase & 4095;
    {
        int c = tid >> 2, j = tid & 3;
        xs[c][j] = x[(size_t)b * CC * NN + (size_t)c * NN + nb + j];
    }
    __syncthreads();
    int o = tid & 63, nl = tid >> 6;
    float p = 0.f, q = 0.f;
    #pragma unroll
    for (int c = 0; c < CC; ++c) {
        float xv = xs[c][nl];
        p = fmaf(xv, Wa[c][o], p);
        q = fmaf(xv, Wb[c][o], q);
    }
    size_t g = (size_t)(nbase + nl);
    g_P[g * OO + o] = p;
    g_Q[g * OO + o] = q;
}

// ---------------------------------------------------------------------------
// Kernel 3: symmetric pd GEMM, compact triangular grid (528 tiles/batch),
// single launch over all batches (blockIdx.z = b). Mirror-stores, emits
// per-32-col chunkmax. Same FMA c-order as sq_kernel => diagonal exactly 0.
// ---------------------------------------------------------------------------
__global__ __launch_bounds__(256) void pd_gemm_sym(const float* __restrict__ x) {
    // linear tile id -> (nt <= mt), t = mt(mt+1)/2 + nt
    int t = blockIdx.x;
    int mt = (int)((sqrtf(8.f * (float)t + 1.f) - 1.f) * 0.5f);
    while ((mt + 1) * (mt + 2) / 2 <= t) ++mt;
    while (mt * (mt + 1) / 2 > t) --mt;
    int nt = t - mt * (mt + 1) / 2;

    __shared__ float As[CC][128];
    __shared__ float Bs[CC][128];
    __shared__ float sqn[128], sqm[128];
    __shared__ float stg[16][128];     // mirror-side chunkmax staging

    int b = blockIdx.z;
    int n0 = nt * 128, m0 = mt * 128;
    const float* xb = x + (size_t)b * CC * NN;
    int tid = threadIdx.x;

    #pragma unroll
    for (int i = 0; i < 8; ++i) {
        int fid = tid + i * 256;
        int c = fid >> 5, v = (fid & 31) << 2;
        *(float4*)&As[c][v] = *(const float4*)&xb[(size_t)c * NN + n0 + v];
        *(float4*)&Bs[c][v] = *(const float4*)&xb[(size_t)c * NN + m0 + v];
    }
    if (tid < 128)       sqn[tid]       = g_sq[b * NN + n0 + tid];
    else                 sqm[tid - 128] = g_sq[b * NN + m0 + (tid - 128)];
    __syncthreads();

    int tx = tid & 15, ty = tid >> 4;
    float acc[8][8];
    #pragma unroll
    for (int i = 0; i < 8; ++i)
        #pragma unroll
        for (int j = 0; j < 8; ++j) acc[i][j] = 0.f;

    #pragma unroll 4
    for (int c = 0; c < CC; ++c) {
        float ar[8], br[8];
        *(float4*)&ar[0] = *(float4*)&As[c][ty * 8];
        *(float4*)&ar[4] = *(float4*)&As[c][ty * 8 + 4];
        *(float4*)&br[0] = *(float4*)&Bs[c][tx * 8];
        *(float4*)&br[4] = *(float4*)&Bs[c][tx * 8 + 4];
        #pragma unroll
        for (int i = 0; i < 8; ++i)
            #pragma unroll
            for (int j = 0; j < 8; ++j)
                acc[i][j] = fmaf(ar[i], br[j], acc[i][j]);
    }

    // normal store: tile [n0.., m0..] + n-side chunk maxima
    float* outp = g_pd + ((size_t)(b * NN + n0)) * NN + m0;
    float* cmn  = g_cmax + ((size_t)(b * NN + n0)) * 128 + (m0 >> 5);
    #pragma unroll
    for (int i = 0; i < 8; ++i) {
        int r = ty * 8 + i;
        float sn = sqn[r];
        float res[8];
        #pragma unroll
        for (int j = 0; j < 8; ++j)
            res[j] = 2.f * acc[i][j] - sn - sqm[tx * 8 + j];
        *(float4*)&outp[(size_t)r * NN + tx * 8]     = *(float4*)&res[0];
        *(float4*)&outp[(size_t)r * NN + tx * 8 + 4] = *(float4*)&res[4];
        float rm = fmaxf(fmaxf(fmaxf(res[0], res[1]), fmaxf(res[2], res[3])),
                         fmaxf(fmaxf(res[4], res[5]), fmaxf(res[6], res[7])));
        rm = fmaxf(rm, __shfl_xor_sync(FULLMASK, rm, 1));
        rm = fmaxf(rm, __shfl_xor_sync(FULLMASK, rm, 2));
        if ((tx & 3) == 0)
            cmn[(size_t)r * 128 + (tx >> 2)] = rm;
    }

    // mirror store: tile [m0.., n0..] + m-side chunk maxima (skip on diagonal)
    if (nt != mt) {
        float* outq = g_pd + ((size_t)(b * NN + m0)) * NN + n0;
        #pragma unroll
        for (int j = 0; j < 8; ++j) {
            int rm = tx * 8 + j;
            float sm = sqm[rm];
            float4 lo, hi;
            lo.x = 2.f * acc[0][j] - sqn[ty * 8 + 0] - sm;
            lo.y = 2.f * acc[1][j] - sqn[ty * 8 + 1] - sm;
            lo.z = 2.f * acc[2][j] - sqn[ty * 8 + 2] - sm;
            lo.w = 2.f * acc[3][j] - sqn[ty * 8 + 3] - sm;
            hi.x = 2.f * acc[4][j] - sqn[ty * 8 + 4] - sm;
            hi.y = 2.f * acc[5][j] - sqn[ty * 8 + 5] - sm;
            hi.z = 2.f * acc[6][j] - sqn[ty * 8 + 6] - sm;
            hi.w = 2.f * acc[7][j] - sqn[ty * 8 + 7] - sm;
            *(float4*)&outq[(size_t)rm * NN + ty * 8]     = lo;
            *(float4*)&outq[(size_t)rm * NN + ty * 8 + 4] = hi;
            float cm = fmaxf(fmaxf(fmaxf(lo.x, lo.y), fmaxf(lo.z, lo.w)),
                             fmaxf(fmaxf(hi.x, hi.y), fmaxf(hi.z, hi.w)));
            stg[ty][rm] = cm;
        }
        __syncthreads();
        if (tid < 128) {
            int col = tid;   // mirror row m0+col
            float* cmm = g_cmax + ((size_t)(b * NN + m0 + col)) * 128 + (n0 >> 5);
            #pragma unroll
            for (int g = 0; g < 4; ++g) {
                float v = fmaxf(fmaxf(stg[g * 4 + 0][col], stg[g * 4 + 1][col]),
                                fmaxf(stg[g * 4 + 2][col], stg[g * 4 + 3][col]));
                cmm[g] = v;
            }
        }
    }
}

// ---------------------------------------------------------------------------
// Kernel 4: warp-per-row top-20 with 2-pass priority chunk visiting:
//   pass 0: chunks with cmax >= s[26] (top-6 lane-group maxes) -> list fills
//           with near-final values, vmin rises fast
//   pass 1: remaining chunks with cmax >= T0 -> mostly skipped by cmv<=vmin
// Fused with gather + BN affine + leaky-relu + max-over-k + transposed store.
// ---------------------------------------------------------------------------
__global__ __launch_bounds__(256) void topk_fused(
    const float* __restrict__ gamma, const float* __restrict__ beta,
    const float* __restrict__ rmean, const float* __restrict__ rvar,
    float* __restrict__ out)
{
    int warp = threadIdx.x >> 5, lane = threadIdx.x & 31;
    int row = blockIdx.x * 8 + warp;        // 0..32767
    int b = row >> 12, n = row & 4095;

    const float* cmrow = g_cmax + (size_t)row * 128;
    float cm[4];
    #pragma unroll
    for (int j = 0; j < 4; ++j) cm[j] = __ldg(&cmrow[j * 32 + lane]);
    float lmax = fmaxf(fmaxf(cm[0], cm[1]), fmaxf(cm[2], cm[3]));

    // bitonic sort 32 lane-group maxes ascending across lanes
    float s = lmax;
    #pragma unroll
    for (int k2 = 2; k2 <= 32; k2 <<= 1) {
        #pragma unroll
        for (int j2 = k2 >> 1; j2 > 0; j2 >>= 1) {
            float o = __shfl_xor_sync(FULLMASK, s, j2);
            bool dirAsc = ((lane & k2) == 0);
            bool upper  = ((lane & j2) == 0);
            float mn = fminf(s, o), mx = fmaxf(s, o);
            s = (dirAsc == upper) ? mn : mx;
        }
    }
    float T0  = __shfl_sync(FULLMASK, s, 32 - KNB);   // 20th largest group max
    float Thi = __shfl_sync(FULLMASK, s, 26);         // 6th largest group max

    float lv = -FLT_MAX;
    int   li = 0;
    float vmin = -FLT_MAX;
    int   minpos = 0;
    const float* rowf = g_pd + (size_t)row * NN;

    #pragma unroll
    for (int pass = 0; pass < 2; ++pass) {
        #pragma unroll
        for (int j = 0; j < 4; ++j) {
            bool sel = (pass == 0) ? (cm[j] >= Thi)
                                   : (cm[j] >= T0 && cm[j] < Thi);
            unsigned cmask = __ballot_sync(FULLMASK, sel);
            while (cmask) {
                int q = __ffs(cmask) - 1;
                cmask &= cmask - 1;
                float cmv = __shfl_sync(FULLMASK, cm[j], q);
                if (cmv <= vmin && vmin > -FLT_MAX) continue;   // can't beat list
                int chunk = j * 32 + q;
                float v = __ldg(&rowf[chunk * 32 + lane]);
                unsigned m = __ballot_sync(FULLMASK, v >= T0 && v > vmin);
                while (m) {
                    int lead = __ffs(m) - 1;
                    float cv = __shfl_sync(FULLMASK, v, lead);
                    int   ci = chunk * 32 + lead;
                    if (lane == minpos) { lv = cv; li = ci; }
                    float tt = (lane < KNB) ? lv : FLT_MAX;
                    #pragma unroll
                    for (int off = 16; off; off >>= 1)
                        tt = fminf(tt, __shfl_xor_sync(FULLMASK, tt, off));
                    vmin = tt;
                    minpos = __ffs(__ballot_sync(FULLMASK, lane < KNB && lv == vmin)) - 1;
                    m &= ~(1u << lead);
                    m &= __ballot_sync(FULLMASK, v > vmin);
                }
            }
        }
    }

    float sc1 = gamma[lane]      * rsqrtf(rvar[lane]      + 1e-5f);
    float sc2 = gamma[lane + 32] * rsqrtf(rvar[lane + 32] + 1e-5f);
    float bi1 = beta[lane]      - rmean[lane]      * sc1;
    float bi2 = beta[lane + 32] - rmean[lane + 32] * sc2;
    float p1 = g_P[(size_t)row * OO + lane];
    float p2 = g_P[(size_t)row * OO + lane + 32];
    const float* Qb = g_Q + (size_t)b * NN * OO;

    float m1 = -FLT_MAX, m2 = -FLT_MAX;
    #pragma unroll
    for (int kk = 0; kk < KNB; ++kk) {
        int nid = __shfl_sync(FULLMASK, li, kk);
        const float* Qr = Qb + (size_t)nid * OO;
        float y1 = (p1 + __ldg(&Qr[lane]))      * sc1 + bi1;
        float y2 = (p2 + __ldg(&Qr[lane + 32])) * sc2 + bi2;
        y1 = (y1 >= 0.f) ? y1 : 0.2f * y1;
        y2 = (y2 >= 0.f) ? y2 : 0.2f * y2;
        m1 = fmaxf(m1, y1);
        m2 = fmaxf(m2, y2);
    }
    out[((size_t)b * OO + lane)      * NN + n] = m1;
    out[((size_t)b * OO + lane + 32) * NN + n] = m2;
}

// ---------------------------------------------------------------------------
// Launcher: single big launches (R6 structure); pq forked onto a side stream
// so its ~8us hides under pd. Event fork/join is graph-capturable.
// ---------------------------------------------------------------------------
extern "C" void kernel_launch(void* const* d_in, const int* in_sizes, int n_in,
                              void* d_out, int out_size) {
    const float* x     = (const float*)d_in[0];
    const float* W     = (const float*)d_in[1];
    const float* gamma = (const float*)d_in[2];
    const float* beta  = (const float*)d_in[3];
    const float* rmean = (const float*)d_in[4];
    const float* rvar  = (const float*)d_in[5];
    float* out = (float*)d_out;

    static cudaStream_t s1;
    static cudaEvent_t evFork, evJoin;
    static int inited = 0;
    if (!inited) {
        cudaStreamCreateWithFlags(&s1, cudaStreamNonBlocking);
        cudaEventCreateWithFlags(&evFork, cudaEventDisableTiming);
        cudaEventCreateWithFlags(&evJoin, cudaEventDisableTiming);
        inited = 1;
    }

    // fork: pq on side stream (independent of sq/pd)
    cudaEventRecord(evFork, 0);
    cudaStreamWaitEvent(s1, evFork, 0);
    pq_kernel<<<8192, 256, 0, s1>>>(x, W);
    cudaEventRecord(evJoin, s1);

    // main stream: sq -> pd
    sq_kernel<<<128, 256>>>(x);
    {
        dim3 grid(528, 1, BB);
        pd_gemm_sym<<<grid, 256>>>(x);
    }

    // join pq before topk
    cudaStreamWaitEvent(0, evJoin, 0);
    topk_fused<<<4096, 256>>>(gamma, beta, rmean, rvar, out);
}

// round 12
// speedup vs baseline: 2.0228x; 1.0188x over previous
#include <cuda_runtime.h>
#include <cfloat>
#include <cstdint>

#define BB 8
#define CC 64
#define NN 4096
#define OO 64
#define KNB 20
#define FULLMASK 0xffffffffu

// Scratch (device globals: allocation-free per harness rules)
__device__ float g_pd[134217728];   // [B*N, N] pairwise "distance", 537MB
__device__ float g_cmax[4194304];   // [B*N, 128] per-32-col-chunk max, 16MB
__device__ float g_sq[32768];       // [B*N] squared norms
__device__ float g_P[2097152];      // [B*N, O]  x·(W1-W2)^T
__device__ float g_Q[2097152];      // [B*N, O]  x·W2^T

// ---------------------------------------------------------------------------
// Kernel 1: squared norms. sq[b,n] = sum_c x[b,c,n]^2 (same FMA order as GEMM)
// ---------------------------------------------------------------------------
__global__ void sq_kernel(const float* __restrict__ x) {
    int t = blockIdx.x * blockDim.x + threadIdx.x;   // 0..32767
    int b = t >> 12, n = t & 4095;
    const float* xp = x + (size_t)b * CC * NN + n;
    float s = 0.f;
    #pragma unroll
    for (int c = 0; c < CC; ++c) {
        float v = xp[(size_t)c * NN];
        s = fmaf(v, v, s);
    }
    g_sq[t] = s;
}

// ---------------------------------------------------------------------------
// Kernel 2: P = x·(W1-W2)^T, Q = x·W2^T   (collapses the edge GEMM)
// ---------------------------------------------------------------------------
__global__ __launch_bounds__(256) void pq_kernel(const float* __restrict__ x,
                                                 const float* __restrict__ W) {
    __shared__ float Wa[CC][OO + 1];
    __shared__ float Wb[CC][OO + 1];
    __shared__ float xs[CC][4];
    int tid = threadIdx.x;
    #pragma unroll
    for (int i = 0; i < 16; ++i) {
        int fid = tid + i * 256;
        int o = fid >> 6, c = fid & 63;
        float w1 = W[o * 128 + c];
        float w2 = W[o * 128 + 64 + c];
        Wa[c][o] = w1 - w2;
        Wb[c][o] = w2;
    }
    int nbase = blockIdx.x * 4;
    int b = nbase >> 12;
    int nb = nbase & 4095;
    {
        int c = tid >> 2, j = tid & 3;
        xs[c][j] = x[(size_t)b * CC * NN + (size_t)c * NN + nb + j];
    }
    __syncthreads();
    int o = tid & 63, nl = tid >> 6;
    float p = 0.f, q = 0.f;
    #pragma unroll
    for (int c = 0; c < CC; ++c) {
        float xv = xs[c][nl];
        p = fmaf(xv, Wa[c][o], p);
        q = fmaf(xv, Wb[c][o], q);
    }
    size_t g = (size_t)(nbase + nl);
    g_P[g * OO + o] = p;
    g_Q[g * OO + o] = q;
}

// ---------------------------------------------------------------------------
// Kernel 3: symmetric pd GEMM, compact triangular grid (528 tiles/batch),
// single launch over all batches (blockIdx.z = b). Mirror-stores, emits
// per-32-col chunkmax. Same FMA c-order as sq_kernel => diagonal exactly 0.
// ---------------------------------------------------------------------------
__global__ __launch_bounds__(256) void pd_gemm_sym(const float* __restrict__ x) {
    // linear tile id -> (nt <= mt), t = mt(mt+1)/2 + nt
    int t = blockIdx.x;
    int mt = (int)((sqrtf(8.f * (float)t + 1.f) - 1.f) * 0.5f);
    while ((mt + 1) * (mt + 2) / 2 <= t) ++mt;
    while (mt * (mt + 1) / 2 > t) --mt;
    int nt = t - mt * (mt + 1) / 2;

    __shared__ float As[CC][128];
    __shared__ float Bs[CC][128];
    __shared__ float sqn[128], sqm[128];
    __shared__ float stg[16][128];     // mirror-side chunkmax staging

    int b = blockIdx.z;
    int n0 = nt * 128, m0 = mt * 128;
    const float* xb = x + (size_t)b * CC * NN;
    int tid = threadIdx.x;

    #pragma unroll
    for (int i = 0; i < 8; ++i) {
        int fid = tid + i * 256;
        int c = fid >> 5, v = (fid & 31) << 2;
        *(float4*)&As[c][v] = *(const float4*)&xb[(size_t)c * NN + n0 + v];
        *(float4*)&Bs[c][v] = *(const float4*)&xb[(size_t)c * NN + m0 + v];
    }
    if (tid < 128)       sqn[tid]       = g_sq[b * NN + n0 + tid];
    else                 sqm[tid - 128] = g_sq[b * NN + m0 + (tid - 128)];
    __syncthreads();

    int tx = tid & 15, ty = tid >> 4;
    float acc[8][8];
    #pragma unroll
    for (int i = 0; i < 8; ++i)
        #pragma unroll
        for (int j = 0; j < 8; ++j) acc[i][j] = 0.f;

    #pragma unroll 4
    for (int c = 0; c < CC; ++c) {
        float ar[8], br[8];
        *(float4*)&ar[0] = *(float4*)&As[c][ty * 8];
        *(float4*)&ar[4] = *(float4*)&As[c][ty * 8 + 4];
        *(float4*)&br[0] = *(float4*)&Bs[c][tx * 8];
        *(float4*)&br[4] = *(float4*)&Bs[c][tx * 8 + 4];
        #pragma unroll
        for (int i = 0; i < 8; ++i)
            #pragma unroll
            for (int j = 0; j < 8; ++j)
                acc[i][j] = fmaf(ar[i], br[j], acc[i][j]);
    }

    // normal store: tile [n0.., m0..] + n-side chunk maxima
    float* outp = g_pd + ((size_t)(b * NN + n0)) * NN + m0;
    float* cmn  = g_cmax + ((size_t)(b * NN + n0)) * 128 + (m0 >> 5);
    #pragma unroll
    for (int i = 0; i < 8; ++i) {
        int r = ty * 8 + i;
        float sn = sqn[r];
        float res[8];
        #pragma unroll
        for (int j = 0; j < 8; ++j)
            res[j] = 2.f * acc[i][j] - sn - sqm[tx * 8 + j];
        *(float4*)&outp[(size_t)r * NN + tx * 8]     = *(float4*)&res[0];
        *(float4*)&outp[(size_t)r * NN + tx * 8 + 4] = *(float4*)&res[4];
        float rm = fmaxf(fmaxf(fmaxf(res[0], res[1]), fmaxf(res[2], res[3])),
                         fmaxf(fmaxf(res[4], res[5]), fmaxf(res[6], res[7])));
        rm = fmaxf(rm, __shfl_xor_sync(FULLMASK, rm, 1));
        rm = fmaxf(rm, __shfl_xor_sync(FULLMASK, rm, 2));
        if ((tx & 3) == 0)
            cmn[(size_t)r * 128 + (tx >> 2)] = rm;
    }

    // mirror store: tile [m0.., n0..] + m-side chunk maxima (skip on diagonal)
    if (nt != mt) {
        float* outq = g_pd + ((size_t)(b * NN + m0)) * NN + n0;
        #pragma unroll
        for (int j = 0; j < 8; ++j) {
            int rm = tx * 8 + j;
            float sm = sqm[rm];
            float4 lo, hi;
            lo.x = 2.f * acc[0][j] - sqn[ty * 8 + 0] - sm;
            lo.y = 2.f * acc[1][j] - sqn[ty * 8 + 1] - sm;
            lo.z = 2.f * acc[2][j] - sqn[ty * 8 + 2] - sm;
            lo.w = 2.f * acc[3][j] - sqn[ty * 8 + 3] - sm;
            hi.x = 2.f * acc[4][j] - sqn[ty * 8 + 4] - sm;
            hi.y = 2.f * acc[5][j] - sqn[ty * 8 + 5] - sm;
            hi.z = 2.f * acc[6][j] - sqn[ty * 8 + 6] - sm;
            hi.w = 2.f * acc[7][j] - sqn[ty * 8 + 7] - sm;
            *(float4*)&outq[(size_t)rm * NN + ty * 8]     = lo;
            *(float4*)&outq[(size_t)rm * NN + ty * 8 + 4] = hi;
            float cm = fmaxf(fmaxf(fmaxf(lo.x, lo.y), fmaxf(lo.z, lo.w)),
                             fmaxf(fmaxf(hi.x, hi.y), fmaxf(hi.z, hi.w)));
            stg[ty][rm] = cm;
        }
        __syncthreads();
        if (tid < 128) {
            int col = tid;   // mirror row m0+col
            float* cmm = g_cmax + ((size_t)(b * NN + m0 + col)) * 128 + (n0 >> 5);
            #pragma unroll
            for (int g = 0; g < 4; ++g) {
                float v = fmaxf(fmaxf(stg[g * 4 + 0][col], stg[g * 4 + 1][col]),
                                fmaxf(stg[g * 4 + 2][col], stg[g * 4 + 3][col]));
                cmm[g] = v;
            }
        }
    }
}

// float -> descending-orderable key (ascending uint sort picks largest first)
__device__ __forceinline__ unsigned int fdesc_key(float v) {
    unsigned int u = __float_as_uint(v);
    u = u ^ (((int)u >> 31) | 0x80000000u);   // ascending-orderable
    return ~u;                                 // descending
}

// ---------------------------------------------------------------------------
// Kernel 4: warp-per-row top-20 via collect-then-sort:
//   1) T0 = 20th-largest chunk-group max (>= 20 elements are >= T0)
//   2) compact all (v >= T0) candidates into a 64-entry smem buffer
//      (independent chunk loads -> full MLP, no serial vmin chain)
//   3) one 64-element bitonic sort of packed keys (~val, idx): entries 0..19
//      are the exact top-20 with JAX tie semantics (value desc, index asc)
//   4) overflow (cnt > 64): fall back to the sequential insert scan
// Fused with gather + BN affine + leaky-relu + max-over-k + transposed store.
// ---------------------------------------------------------------------------
__global__ __launch_bounds__(256) void topk_fused(
    const float* __restrict__ gamma, const float* __restrict__ beta,
    const float* __restrict__ rmean, const float* __restrict__ rvar,
    float* __restrict__ out)
{
    __shared__ unsigned long long buf[8][64];
    int warp = threadIdx.x >> 5, lane = threadIdx.x & 31;
    int row = blockIdx.x * 8 + warp;        // 0..32767
    int b = row >> 12, n = row & 4095;

    const float* cmrow = g_cmax + (size_t)row * 128;
    float cm[4];
    #pragma unroll
    for (int j = 0; j < 4; ++j) cm[j] = __ldg(&cmrow[j * 32 + lane]);
    float lmax = fmaxf(fmaxf(cm[0], cm[1]), fmaxf(cm[2], cm[3]));

    // bitonic sort 32 lane-group maxes ascending across lanes
    float s = lmax;
    #pragma unroll
    for (int k2 = 2; k2 <= 32; k2 <<= 1) {
        #pragma unroll
        for (int j2 = k2 >> 1; j2 > 0; j2 >>= 1) {
            float o = __shfl_xor_sync(FULLMASK, s, j2);
            bool dirAsc = ((lane & k2) == 0);
            bool upper  = ((lane & j2) == 0);
            float mn = fminf(s, o), mx = fmaxf(s, o);
            s = (dirAsc == upper) ? mn : mx;
        }
    }
    float T0 = __shfl_sync(FULLMASK, s, 32 - KNB);   // 20th largest group max

    const float* rowf = g_pd + (size_t)row * NN;
    unsigned lanelt = (1u << lane) - 1u;

    // ---- collect candidates v >= T0 into smem buffer
    int cnt = 0;
    #pragma unroll
    for (int j = 0; j < 4; ++j) {
        unsigned cmask = __ballot_sync(FULLMASK, cm[j] >= T0);
        while (cmask) {
            int q = __ffs(cmask) - 1;
            cmask &= cmask - 1;
            int chunk = j * 32 + q;
            float v = __ldg(&rowf[chunk * 32 + lane]);
            unsigned m = __ballot_sync(FULLMASK, v >= T0);
            int pos = cnt + __popc(m & lanelt);
            if (v >= T0 && pos < 64) {
                unsigned long long key =
                    ((unsigned long long)fdesc_key(v) << 32)
                    | (unsigned int)(chunk * 32 + lane);
                buf[warp][pos] = key;
            }
            cnt += __popc(m);
        }
    }

    int li = 0;   // lanes 0..19 will hold the top-20 indices
    if (cnt <= 64) {
        // ---- 64-element bitonic sort (2 keys/lane, vi = r*32 + lane)
        const unsigned long long PADK = 0xFFFFFFFFFFFFFFFFull;
        unsigned long long e0 = (lane      < cnt) ? buf[warp][lane]      : PADK;
        unsigned long long e1 = (lane + 32 < cnt) ? buf[warp][lane + 32] : PADK;
        #pragma unroll
        for (int k2 = 2; k2 <= 64; k2 <<= 1) {
            #pragma unroll
            for (int j2 = k2 >> 1; j2 > 0; j2 >>= 1) {
                if (j2 == 32) {
                    // partner is the other register, same lane; dir always asc
                    unsigned long long lo = e0 < e1 ? e0 : e1;
                    unsigned long long hi = e0 < e1 ? e1 : e0;
                    e0 = lo; e1 = hi;
                } else {
                    bool up = ((lane & j2) == 0);
                    // r = 0
                    {
                        bool asc = ((lane & k2) == 0) || (k2 == 64);
                        unsigned long long o =
                            __shfl_xor_sync(FULLMASK, e0, j2);
                        unsigned long long mn = e0 < o ? e0 : o;
                        unsigned long long mx = e0 < o ? o : e0;
                        e0 = (asc == up) ? mn : mx;
                    }
                    // r = 1 (vi = lane + 32)
                    {
                        bool asc = (((lane + 32) & k2) == 0) || (k2 == 64);
                        unsigned long long o =
                            __shfl_xor_sync(FULLMASK, e1, j2);
                        unsigned long long mn = e1 < o ? e1 : o;
                        unsigned long long mx = e1 < o ? o : e1;
                        e1 = (asc == up) ? mn : mx;
                    }
                }
            }
        }
        li = (int)(unsigned int)(e0 & 0xFFFFFFFFull);   // valid for lane < 20
    } else {
        // ---- rare overflow: exact sequential insert scan (proven path)
        float lv = -FLT_MAX;
        float vmin = -FLT_MAX;
        int   minpos = 0;
        #pragma unroll
        for (int j = 0; j < 4; ++j) {
            unsigned cmask = __ballot_sync(FULLMASK, cm[j] >= T0);
            while (cmask) {
                int q = __ffs(cmask) - 1;
                cmask &= cmask - 1;
                float cmv = __shfl_sync(FULLMASK, cm[j], q);
                if (cmv <= vmin && vmin > -FLT_MAX) continue;
                int chunk = j * 32 + q;
                float v = __ldg(&rowf[chunk * 32 + lane]);
                unsigned m = __ballot_sync(FULLMASK, v >= T0 && v > vmin);
                while (m) {
                    int lead = __ffs(m) - 1;
                    float cv = __shfl_sync(FULLMASK, v, lead);
                    int   ci = chunk * 32 + lead;
                    if (lane == minpos) { lv = cv; li = ci; }
                    float tt = (lane < KNB) ? lv : FLT_MAX;
                    #pragma unroll
                    for (int off = 16; off; off >>= 1)
                        tt = fminf(tt, __shfl_xor_sync(FULLMASK, tt, off));
                    vmin = tt;
                    minpos = __ffs(__ballot_sync(FULLMASK,
                                                 lane < KNB && lv == vmin)) - 1;
                    m &= ~(1u << lead);
                    m &= __ballot_sync(FULLMASK, v > vmin);
                }
            }
        }
    }

    // ---- fused epilogue: out[b,o,n] = max_k leaky(BN(P[row,o] + Q[idx_k,o]))
    float sc1 = gamma[lane]      * rsqrtf(rvar[lane]      + 1e-5f);
    float sc2 = gamma[lane + 32] * rsqrtf(rvar[lane + 32] + 1e-5f);
    float bi1 = beta[lane]      - rmean[lane]      * sc1;
    float bi2 = beta[lane + 32] - rmean[lane + 32] * sc2;
    float p1 = g_P[(size_t)row * OO + lane];
    float p2 = g_P[(size_t)row * OO + lane + 32];
    const float* Qb = g_Q + (size_t)b * NN * OO;

    float m1 = -FLT_MAX, m2 = -FLT_MAX;
    #pragma unroll
    for (int kk = 0; kk < KNB; ++kk) {
        int nid = __shfl_sync(FULLMASK, li, kk);
        const float* Qr = Qb + (size_t)nid * OO;
        float y1 = (p1 + __ldg(&Qr[lane]))      * sc1 + bi1;
        float y2 = (p2 + __ldg(&Qr[lane + 32])) * sc2 + bi2;
        y1 = (y1 >= 0.f) ? y1 : 0.2f * y1;
        y2 = (y2 >= 0.f) ? y2 : 0.2f * y2;
        m1 = fmaxf(m1, y1);
        m2 = fmaxf(m2, y2);
    }
    out[((size_t)b * OO + lane)      * NN + n] = m1;
    out[((size_t)b * OO + lane + 32) * NN + n] = m2;
}

// ---------------------------------------------------------------------------
extern "C" void kernel_launch(void* const* d_in, const int* in_sizes, int n_in,
                              void* d_out, int out_size) {
    const float* x     = (const float*)d_in[0];
    const float* W     = (const float*)d_in[1];
    const float* gamma = (const float*)d_in[2];
    const float* beta  = (const float*)d_in[3];
    const float* rmean = (const float*)d_in[4];
    const float* rvar  = (const float*)d_in[5];
    float* out = (float*)d_out;

    sq_kernel<<<128, 256>>>(x);
    pq_kernel<<<8192, 256>>>(x, W);
    {
        dim3 grid(528, 1, BB);
        pd_gemm_sym<<<grid, 256>>>(x);
    }
    topk_fused<<<4096, 256>>>(gamma, beta, rmean, rvar, out);
}